// round 5
// baseline (speedup 1.0000x reference)
#include <cuda_runtime.h>
#include <cuda_bf16.h>
#include <cstdint>

#define BB   512
#define SEQL 512
#define IND  128
#define HID  256
#define TT   24
#define TEMP 64

// ---------------- persistent device scratch (no allocations) ----------------
__device__ __nv_bfloat16 g_H16[(size_t)BB * SEQL * IND];        // 67 MB
__device__ __nv_bfloat16 g_Wa16[IND * TT * TEMP];               // 384 KB
__device__ __nv_bfloat16 g_S16[(size_t)TT * BB * SEQL * TEMP];  // 805 MB: S[t][b][l][k]
__device__ float g_h[BB * HID];
__device__ float g_c[BB * HID];
__device__ float g_y[BB];
__device__ float g_ctx[BB * IND];
__device__ float g_gates[BB * 4 * HID];

// ---------------- asm helpers ----------------
__device__ __forceinline__ void ldsm4(uint32_t* r, uint32_t a) {
    asm volatile("ldmatrix.sync.aligned.m8n8.x4.shared.b16 {%0,%1,%2,%3}, [%4];\n"
        : "=r"(r[0]), "=r"(r[1]), "=r"(r[2]), "=r"(r[3]) : "r"(a));
}
__device__ __forceinline__ void ldsm4t(uint32_t* r, uint32_t a) {
    asm volatile("ldmatrix.sync.aligned.m8n8.x4.trans.shared.b16 {%0,%1,%2,%3}, [%4];\n"
        : "=r"(r[0]), "=r"(r[1]), "=r"(r[2]), "=r"(r[3]) : "r"(a));
}
__device__ __forceinline__ void mma_bf16(float* d, const uint32_t* a, const uint32_t* b) {
    asm volatile("mma.sync.aligned.m16n8k16.row.col.f32.bf16.bf16.f32 "
        "{%0,%1,%2,%3}, {%4,%5,%6,%7}, {%8,%9}, {%0,%1,%2,%3};\n"
        : "+f"(d[0]), "+f"(d[1]), "+f"(d[2]), "+f"(d[3])
        : "r"(a[0]), "r"(a[1]), "r"(a[2]), "r"(a[3]), "r"(b[0]), "r"(b[1]));
}
__device__ __forceinline__ void mma_tf32(float* d, const uint32_t* a, uint32_t b0, uint32_t b1) {
    asm volatile("mma.sync.aligned.m16n8k8.row.col.f32.tf32.tf32.f32 "
        "{%0,%1,%2,%3}, {%4,%5,%6,%7}, {%8,%9}, {%0,%1,%2,%3};\n"
        : "+f"(d[0]), "+f"(d[1]), "+f"(d[2]), "+f"(d[3])
        : "r"(a[0]), "r"(a[1]), "r"(a[2]), "r"(a[3]), "r"(b0), "r"(b1));
}
__device__ __forceinline__ uint32_t f2tf32(float v) {
    uint32_t u; asm("cvt.rna.tf32.f32 %0, %1;" : "=r"(u) : "f"(v)); return u;
}
__device__ __forceinline__ float fast_tanh(float x) {
    float r; asm("tanh.approx.f32 %0, %1;" : "=f"(r) : "f"(x)); return r;
}
__device__ __forceinline__ void cp_async16(uint32_t dst, const void* src) {
    asm volatile("cp.async.cg.shared.global [%0], [%1], 16;\n" :: "r"(dst), "l"(src));
}
__device__ __forceinline__ void cp_commit() {
    asm volatile("cp.async.commit_group;\n" ::: "memory");
}
template<int N> __device__ __forceinline__ void cp_wait() {
    asm volatile("cp.async.wait_group %0;\n" :: "n"(N) : "memory");
}
__device__ __forceinline__ uint32_t pack_bf16x2(float a, float b) {
    __nv_bfloat162 p = __floats2bfloat162_rn(a, b);
    return *(const uint32_t*)&p;
}

// ---------------- kernel 0a: H fp32 -> bf16 ----------------
__global__ void convert_H(const float* __restrict__ H) {
    int i = blockIdx.x * blockDim.x + threadIdx.x;
    float4 v = ((const float4*)H)[i];
    uint2 o;
    o.x = pack_bf16x2(v.x, v.y);
    o.y = pack_bf16x2(v.z, v.w);
    ((uint2*)g_H16)[i] = o;
}
// ---------------- kernel 0b: Wa fp32 -> bf16 ----------------
__global__ void convert_Wa(const float* __restrict__ Wa) {
    int i = blockIdx.x * blockDim.x + threadIdx.x;
    float4 v = ((const float4*)Wa)[i];
    uint2 o;
    o.x = pack_bf16x2(v.x, v.y);
    o.y = pack_bf16x2(v.z, v.w);
    ((uint2*)g_Wa16)[i] = o;
}

// ---------------- kernel 1: init state ----------------
__global__ void init_state(const float* __restrict__ emb, const float* __restrict__ y0) {
    int b = blockIdx.x, j = threadIdx.x;
    g_h[b * HID + j] = emb[b * 2 * HID + j];
    g_c[b * HID + j] = emb[b * 2 * HID + HID + j];
    if (j == 0) g_y[b] = y0[b];
}

// ---------------- kernel 2: one-shot S = H @ Wa (bf16 mma) ----------------
// C[M=262144, N=1536], K=128. Block tile 128x128, 8 warps (4m x 2n).
#define SG_STRIDE 136
#define SGEMM_SMEM (2 * 128 * SG_STRIDE * 2)

__global__ __launch_bounds__(256, 2) void sgemm_kernel() {
    extern __shared__ char smraw[];
    __nv_bfloat16* sA = (__nv_bfloat16*)smraw;        // [128][136]
    __nv_bfloat16* sB = sA + 128 * SG_STRIDE;         // [128][136]
    uint32_t aBase = (uint32_t)__cvta_generic_to_shared(sA);
    uint32_t bBase = (uint32_t)__cvta_generic_to_shared(sB);

    int tid = threadIdx.x, warp = tid >> 5, lane = tid & 31;
    int wm = warp & 3, wn = warp >> 2;
    int n0 = blockIdx.x * 128, m0 = blockIdx.y * 128;

    // FULL tile loads: 2048 16B chunks EACH for A and B (was the R4 bug)
    #pragma unroll
    for (int i = tid; i < 2048; i += 256) {
        int row = i >> 4, seg = i & 15;    // 16 chunks of 8 bf16 = 128 cols
        cp_async16(aBase + (uint32_t)(row * SG_STRIDE + seg * 8) * 2,
                   g_H16 + (size_t)(m0 + row) * IND + seg * 8);
    }
    #pragma unroll
    for (int i = tid; i < 2048; i += 256) {
        int row = i >> 4, seg = i & 15;
        cp_async16(bBase + (uint32_t)(row * SG_STRIDE + seg * 8) * 2,
                   g_Wa16 + (size_t)row * (TT * TEMP) + n0 + seg * 8);
    }
    cp_commit();
    cp_wait<0>();
    __syncthreads();

    float acc[2][8][4];
    #pragma unroll
    for (int mi = 0; mi < 2; mi++)
        #pragma unroll
        for (int ni = 0; ni < 8; ni++)
            #pragma unroll
            for (int r = 0; r < 4; r++) acc[mi][ni][r] = 0.f;

    int lr = lane & 7, lg = (lane >> 3) & 1, lc = lane >> 4;
    #pragma unroll
    for (int ks = 0; ks < 8; ks++) {
        uint32_t afr[2][4];
        #pragma unroll
        for (int mi = 0; mi < 2; mi++) {
            int row = wm * 32 + mi * 16 + lr + lg * 8;
            ldsm4(afr[mi], aBase + (uint32_t)(row * SG_STRIDE + ks * 16 + lc * 8) * 2);
        }
        uint32_t bfr[4][4];
        #pragma unroll
        for (int p = 0; p < 4; p++) {
            int row = ks * 16 + lr + lg * 8;
            int col = wn * 64 + p * 16 + lc * 8;
            ldsm4t(bfr[p], bBase + (uint32_t)(row * SG_STRIDE + col) * 2);
        }
        #pragma unroll
        for (int mi = 0; mi < 2; mi++)
            #pragma unroll
            for (int p = 0; p < 4; p++) {
                mma_bf16(acc[mi][2 * p],     afr[mi], &bfr[p][0]);
                mma_bf16(acc[mi][2 * p + 1], afr[mi], &bfr[p][2]);
            }
    }
    __syncthreads();

    // stage C as bf16 into sA, then coalesced scattered write to g_S16[t][b][l][k]
    #pragma unroll
    for (int mi = 0; mi < 2; mi++)
        #pragma unroll
        for (int ni = 0; ni < 8; ni++) {
            int row = wm * 32 + mi * 16 + (lane >> 2);
            int col = wn * 64 + ni * 8 + 2 * (lane & 3);
            *(uint32_t*)(sA + row * SG_STRIDE + col)       = pack_bf16x2(acc[mi][ni][0], acc[mi][ni][1]);
            *(uint32_t*)(sA + (row + 8) * SG_STRIDE + col) = pack_bf16x2(acc[mi][ni][2], acc[mi][ni][3]);
        }
    __syncthreads();

    int t0 = blockIdx.x * 2;
    #pragma unroll
    for (int i = tid; i < 2048; i += 256) {
        int row = i >> 4, half = (i >> 3) & 1, seg = i & 7;
        uint4 v = *(const uint4*)(sA + row * SG_STRIDE + half * 64 + seg * 8);
        int m = m0 + row;
        int b = m >> 9, l = m & 511;
        size_t dst = (((size_t)(t0 + half) * BB + b) * SEQL + l) * TEMP + seg * 8;
        *(uint4*)(g_S16 + dst) = v;
    }
}

// ---------------- kernel 3: per-step attention epilogue ----------------
__global__ __launch_bounds__(256) void attn_kernel(
    const float* __restrict__ Ua, const float* __restrict__ ba,
    const float* __restrict__ Va, int t)
{
    __shared__ float2 sVC[64];      // (Va[k], cUa[k]+ba[k])
    __shared__ float  spart[256];
    __shared__ float  se[512];
    __shared__ float  sctxp[2048];
    __shared__ float  sred[16];

    int b = blockIdx.x, tid = threadIdx.x;
    int warp = tid >> 5, lane = tid & 31;

    // cUa partials: 4 partitions x 64 k
    {
        int k = tid & 63, part = tid >> 6;
        const float* Uc = Ua + (size_t)t * 64 + k;
        const float* cb = g_c + b * HID;
        float a = 0.f;
        int j0 = part * 64;
        #pragma unroll 8
        for (int j = j0; j < j0 + 64; j++) a += cb[j] * Uc[(size_t)j * (TT * 64)];
        spart[part * 64 + k] = a;
    }
    __syncthreads();
    if (tid < 64) {
        float cb = ba[t * 64 + tid] + spart[tid] + spart[64 + tid] + spart[128 + tid] + spart[192 + tid];
        sVC[tid] = make_float2(Va[tid * TT + t], cb);
    }
    __syncthreads();

    // e[l] = sum_k Va[k] * tanh(S[t,b,l,k] + cUa[k] + ba[k])
    const uint4* Sp = (const uint4*)(g_S16 + (((size_t)t * BB + b) * SEQL) * TEMP);
    #pragma unroll
    for (int r = 0; r < 2; r++) {
        int l = tid + r * 256;
        float el = 0.f;
        #pragma unroll
        for (int j = 0; j < 8; j++) {
            uint4 v = Sp[l * 8 + j];
            const __nv_bfloat162* h2 = (const __nv_bfloat162*)&v;
            #pragma unroll
            for (int ii = 0; ii < 4; ii++) {
                float2 f = __bfloat1622float2(h2[ii]);
                int k0 = j * 8 + ii * 2;
                float2 vc0 = sVC[k0], vc1 = sVC[k0 + 1];
                el += vc0.x * fast_tanh(f.x + vc0.y);
                el += vc1.x * fast_tanh(f.y + vc1.y);
            }
        }
        se[l] = el;
    }
    __syncthreads();

    // softmax over 512 (scale 1/16)
    float e0 = se[tid], e1 = se[tid + 256];
    float m = fmaxf(e0, e1);
    #pragma unroll
    for (int off = 16; off; off >>= 1) m = fmaxf(m, __shfl_xor_sync(0xffffffffu, m, off));
    if (lane == 0) sred[warp] = m;
    __syncthreads();
    float M = fmaxf(fmaxf(fmaxf(sred[0], sred[1]), fmaxf(sred[2], sred[3])),
                    fmaxf(fmaxf(sred[4], sred[5]), fmaxf(sred[6], sred[7])));
    float v0 = __expf((e0 - M) * 0.0625f);
    float v1 = __expf((e1 - M) * 0.0625f);
    float s = v0 + v1;
    #pragma unroll
    for (int off = 16; off; off >>= 1) s += __shfl_xor_sync(0xffffffffu, s, off);
    if (lane == 0) sred[8 + warp] = s;
    se[tid] = v0; se[tid + 256] = v1;
    __syncthreads();
    float inv = 1.f / (sred[8] + sred[9] + sred[10] + sred[11] +
                       sred[12] + sred[13] + sred[14] + sred[15]);

    // ctx[d] = sum_l beta[l] * H[b,l,d]
    {
        int q = tid & 15, part = tid >> 4;
        const uint4* Hp = (const uint4*)(g_H16 + (size_t)b * SEQL * IND);
        float a[8] = {0.f, 0.f, 0.f, 0.f, 0.f, 0.f, 0.f, 0.f};
        #pragma unroll 4
        for (int l = part; l < SEQL; l += 16) {
            float bl = se[l];
            uint4 v = Hp[l * 16 + q];     // 16 uint4 per 128-col row; thread q -> d in [8q, 8q+8)
            const __nv_bfloat162* h2 = (const __nv_bfloat162*)&v;
            #pragma unroll
            for (int i = 0; i < 4; i++) {
                float2 f = __bfloat1622float2(h2[i]);
                a[2 * i]     += bl * f.x;
                a[2 * i + 1] += bl * f.y;
            }
        }
        #pragma unroll
        for (int i = 0; i < 8; i++) sctxp[part * 128 + q * 8 + i] = a[i];
        __syncthreads();
        if (tid < 128) {
            float sum = 0.f;
            #pragma unroll
            for (int p = 0; p < 16; p++) sum += sctxp[p * 128 + tid];
            g_ctx[b * IND + tid] = sum * inv;
        }
    }
}

// ---------------- kernel 4: gates via tf32 mma (rna), cp.async 2-stage ----------------
__global__ __launch_bounds__(256) void gates_kernel(
    const float* __restrict__ W, const float* __restrict__ U,
    const float* __restrict__ bias, const float* __restrict__ Wy, int t)
{
    __shared__ float As[2][64][36];
    __shared__ float Bs[2][32][72];
    int tid = threadIdx.x;
    int warp = tid >> 5, lane = tid & 31;
    int wm = warp & 3, wn = warp >> 2;
    int n0 = blockIdx.x * 64, b0 = blockIdx.y * 64;
    float acc[4][4] = {};

    auto copy_chunk = [&](int kc, int buf) {
        #pragma unroll
        for (int i = tid; i < 512; i += 256) {
            int row = i >> 3, seg = i & 7;
            const float* src = (kc < 4)
                ? (g_ctx + (size_t)(b0 + row) * IND + kc * 32 + seg * 4)
                : (g_h   + (size_t)(b0 + row) * HID + (kc * 32 - IND) + seg * 4);
            cp_async16((uint32_t)__cvta_generic_to_shared(&As[buf][row][seg * 4]), src);
        }
        #pragma unroll
        for (int i = tid; i < 512; i += 256) {
            int k = i >> 4, seg = i & 15;
            int kg = kc * 32 + k;
            const float* src = (kg < IND)
                ? (W + (size_t)kg * (TT * 1024) + (size_t)t * 1024 + n0 + seg * 4)
                : (U + (size_t)(kg - IND) * (TT * 1024) + (size_t)t * 1024 + n0 + seg * 4);
            cp_async16((uint32_t)__cvta_generic_to_shared(&Bs[buf][k][seg * 4]), src);
        }
    };

    copy_chunk(0, 0); cp_commit();
    copy_chunk(1, 1); cp_commit();

    for (int kc = 0; kc < 12; kc++) {
        cp_wait<1>();
        __syncthreads();
        int buf = kc & 1;
        int ar = wm * 16 + (lane >> 2);
        int bk = lane & 3;
        int bn = wn * 32 + (lane >> 2);
        #pragma unroll
        for (int ks = 0; ks < 4; ks++) {
            uint32_t a[4];
            int ac = ks * 8 + (lane & 3);
            a[0] = f2tf32(As[buf][ar][ac]);
            a[1] = f2tf32(As[buf][ar + 8][ac]);
            a[2] = f2tf32(As[buf][ar][ac + 4]);
            a[3] = f2tf32(As[buf][ar + 8][ac + 4]);
            #pragma unroll
            for (int nt = 0; nt < 4; nt++) {
                uint32_t b0r = f2tf32(Bs[buf][ks * 8 + bk][bn + nt * 8]);
                uint32_t b1r = f2tf32(Bs[buf][ks * 8 + bk + 4][bn + nt * 8]);
                mma_tf32(acc[nt], a, b0r, b1r);
            }
        }
        __syncthreads();
        if (kc + 2 < 12) copy_chunk(kc + 2, buf);
        cp_commit();
    }

    int r0 = b0 + wm * 16 + (lane >> 2);
    float y0v = g_y[r0], y1v = g_y[r0 + 8];
    #pragma unroll
    for (int nt = 0; nt < 4; nt++) {
        int n = n0 + wn * 32 + nt * 8 + (lane & 3) * 2;
        float bb0 = bias[t * 1024 + n],   bb1 = bias[t * 1024 + n + 1];
        float wy0 = Wy[t * 1024 + n],     wy1 = Wy[t * 1024 + n + 1];
        g_gates[(size_t)r0 * 1024 + n]           = acc[nt][0] + bb0 + y0v * wy0;
        g_gates[(size_t)r0 * 1024 + n + 1]       = acc[nt][1] + bb1 + y0v * wy1;
        g_gates[(size_t)(r0 + 8) * 1024 + n]     = acc[nt][2] + bb0 + y1v * wy0;
        g_gates[(size_t)(r0 + 8) * 1024 + n + 1] = acc[nt][3] + bb1 + y1v * wy1;
    }
}

// ---------------- kernel 5: cell update + y projection ----------------
__global__ void update_kernel(const float* __restrict__ fcw, const float* __restrict__ fcb,
                              int t, float* __restrict__ outy, float* __restrict__ outh)
{
    __shared__ float red[8];
    int b = blockIdx.x, j = threadIdx.x;
    size_t gi = (size_t)b * 1024;
    float i_ = 1.f / (1.f + __expf(-g_gates[gi + j]));
    float f_ = 1.f / (1.f + __expf(-g_gates[gi + 256 + j]));
    float gv = tanhf(g_gates[gi + 512 + j]);
    float o_ = 1.f / (1.f + __expf(-g_gates[gi + 768 + j]));
    float c = f_ * g_c[b * HID + j] + i_ * gv;
    float h = o_ * tanhf(c);
    g_c[b * HID + j] = c;
    g_h[b * HID + j] = h;
    outh[(size_t)b * TT * HID + (size_t)t * HID + j] = h;

    float p = h * fcw[t * HID + j];
    #pragma unroll
    for (int off = 16; off; off >>= 1) p += __shfl_xor_sync(0xffffffffu, p, off);
    int lane = j & 31, w = j >> 5;
    if (lane == 0) red[w] = p;
    __syncthreads();
    if (j == 0) {
        float ssum = red[0] + red[1] + red[2] + red[3] +
                     red[4] + red[5] + red[6] + red[7] + fcb[t];
        g_y[b] = ssum;
        outy[b * TT + t] = ssum;
    }
}

// ---------------- launch ----------------
extern "C" void kernel_launch(void* const* d_in, const int* in_sizes, int n_in,
                              void* d_out, int out_size)
{
    const float* H    = (const float*)d_in[0];
    const float* y0   = (const float*)d_in[1];
    const float* emb  = (const float*)d_in[2];
    const float* Wa   = (const float*)d_in[3];
    const float* Ua   = (const float*)d_in[4];
    const float* ba   = (const float*)d_in[5];
    const float* Va   = (const float*)d_in[6];
    const float* W    = (const float*)d_in[7];
    const float* U    = (const float*)d_in[8];
    const float* bias = (const float*)d_in[9];
    const float* Wy   = (const float*)d_in[10];
    const float* fcw  = (const float*)d_in[11];
    const float* fcb  = (const float*)d_in[12];

    float* outy = (float*)d_out;                 // (B, 24)
    float* outh = outy + (size_t)BB * TT;        // (B, 24, 256)

    cudaFuncSetAttribute(sgemm_kernel, cudaFuncAttributeMaxDynamicSharedMemorySize, SGEMM_SMEM);

    convert_H<<<(BB * SEQL * IND / 4) / 256, 256>>>(H);
    convert_Wa<<<(IND * TT * TEMP / 4) / 256, 256>>>(Wa);
    init_state<<<BB, 256>>>(emb, y0);
    sgemm_kernel<<<dim3(12, 2048), 256, SGEMM_SMEM>>>();
    for (int t = 0; t < TT; t++) {
        attn_kernel<<<BB, 256>>>(Ua, ba, Va, t);
        gates_kernel<<<dim3(16, 8), 256>>>(W, U, bias, Wy, t);
        update_kernel<<<BB, 256>>>(fcw, fcb, t, outy, outh);
    }
}

// round 6
// speedup vs baseline: 1.5278x; 1.5278x over previous
#include <cuda_runtime.h>
#include <cuda_bf16.h>
#include <cuda_fp16.h>
#include <cstdint>

#define BB   512
#define SEQL 512
#define IND  128
#define HID  256
#define TT   24
#define TEMP 64

// ---------------- persistent device scratch (no allocations) ----------------
__device__ __nv_bfloat16 g_H16[(size_t)BB * SEQL * IND];   // 67 MB, L2-resident
__device__ __nv_bfloat16 g_Wa16[IND * TT * TEMP];          // 384 KB
__device__ float g_h[BB * HID];
__device__ float g_c[BB * HID];
__device__ float g_y[BB];
__device__ float g_cua[BB * TEMP];                         // c_t @ Ua_t for current step
__device__ float g_e[BB * SEQL];                           // attention logits (1 MB)
__device__ float g_ctx[BB * IND];
__device__ float g_gates[BB * 4 * HID];

// ---------------- asm helpers ----------------
__device__ __forceinline__ void ldsm4(uint32_t* r, uint32_t a) {
    asm volatile("ldmatrix.sync.aligned.m8n8.x4.shared.b16 {%0,%1,%2,%3}, [%4];\n"
        : "=r"(r[0]), "=r"(r[1]), "=r"(r[2]), "=r"(r[3]) : "r"(a));
}
__device__ __forceinline__ void ldsm4t(uint32_t* r, uint32_t a) {
    asm volatile("ldmatrix.sync.aligned.m8n8.x4.trans.shared.b16 {%0,%1,%2,%3}, [%4];\n"
        : "=r"(r[0]), "=r"(r[1]), "=r"(r[2]), "=r"(r[3]) : "r"(a));
}
__device__ __forceinline__ void mma_bf16(float* d, const uint32_t* a, const uint32_t* b) {
    asm volatile("mma.sync.aligned.m16n8k16.row.col.f32.bf16.bf16.f32 "
        "{%0,%1,%2,%3}, {%4,%5,%6,%7}, {%8,%9}, {%0,%1,%2,%3};\n"
        : "+f"(d[0]), "+f"(d[1]), "+f"(d[2]), "+f"(d[3])
        : "r"(a[0]), "r"(a[1]), "r"(a[2]), "r"(a[3]), "r"(b[0]), "r"(b[1]));
}
__device__ __forceinline__ void mma_tf32(float* d, const uint32_t* a, uint32_t b0, uint32_t b1) {
    asm volatile("mma.sync.aligned.m16n8k8.row.col.f32.tf32.tf32.f32 "
        "{%0,%1,%2,%3}, {%4,%5,%6,%7}, {%8,%9}, {%0,%1,%2,%3};\n"
        : "+f"(d[0]), "+f"(d[1]), "+f"(d[2]), "+f"(d[3])
        : "r"(a[0]), "r"(a[1]), "r"(a[2]), "r"(a[3]), "r"(b0), "r"(b1));
}
__device__ __forceinline__ uint32_t f2tf32(float v) {
    uint32_t u; asm("cvt.rna.tf32.f32 %0, %1;" : "=r"(u) : "f"(v)); return u;
}
// packed fp16x2 tanh: returns (tanh x0, tanh x1)
__device__ __forceinline__ float2 tanh2(float x0, float x1) {
    uint32_t r;
    asm("{\n\t.reg .b32 p;\n\tcvt.rn.f16x2.f32 p, %1, %2;\n\ttanh.approx.f16x2 %0, p;\n\t}"
        : "=r"(r) : "f"(x1), "f"(x0));
    __half2 h = *reinterpret_cast<__half2*>(&r);
    return __half22float2(h);
}
__device__ __forceinline__ void cp_async16(uint32_t dst, const void* src) {
    asm volatile("cp.async.cg.shared.global [%0], [%1], 16;\n" :: "r"(dst), "l"(src));
}
__device__ __forceinline__ void cp_commit() {
    asm volatile("cp.async.commit_group;\n" ::: "memory");
}
template<int N> __device__ __forceinline__ void cp_wait() {
    asm volatile("cp.async.wait_group %0;\n" :: "n"(N) : "memory");
}
__device__ __forceinline__ uint32_t pack_bf16x2(float a, float b) {
    __nv_bfloat162 p = __floats2bfloat162_rn(a, b);
    return *(const uint32_t*)&p;
}

// ---------------- kernel 0a/0b: fp32 -> bf16 converts ----------------
__global__ void convert_H(const float* __restrict__ H) {
    int i = blockIdx.x * blockDim.x + threadIdx.x;
    float4 v = ((const float4*)H)[i];
    uint2 o;
    o.x = pack_bf16x2(v.x, v.y);
    o.y = pack_bf16x2(v.z, v.w);
    ((uint2*)g_H16)[i] = o;
}
__global__ void convert_Wa(const float* __restrict__ Wa) {
    int i = blockIdx.x * blockDim.x + threadIdx.x;
    float4 v = ((const float4*)Wa)[i];
    uint2 o;
    o.x = pack_bf16x2(v.x, v.y);
    o.y = pack_bf16x2(v.z, v.w);
    ((uint2*)g_Wa16)[i] = o;
}

// ---------------- kernel 1: init state ----------------
__global__ void init_state(const float* __restrict__ emb, const float* __restrict__ y0) {
    int b = blockIdx.x, j = threadIdx.x;
    g_h[b * HID + j] = emb[b * 2 * HID + j];
    g_c[b * HID + j] = emb[b * 2 * HID + HID + j];
    if (j == 0) g_y[b] = y0[b];
}

// ---------------- kernel 1b: cUa for t=0 ----------------
__global__ void cua_init(const float* __restrict__ Ua) {
    __shared__ float sp[256];
    int b = blockIdx.x, tid = threadIdx.x;
    int k = tid & 63, part = tid >> 6;
    const float* Uc = Ua + k;              // t = 0
    const float* cb = g_c + b * HID;
    float a = 0.f;
    int j0 = part * 64;
    #pragma unroll 8
    for (int j = j0; j < j0 + 64; j++) a += cb[j] * Uc[(size_t)j * (TT * 64)];
    sp[part * 64 + k] = a;
    __syncthreads();
    if (tid < 64) g_cua[b * 64 + tid] = sp[tid] + sp[64 + tid] + sp[128 + tid] + sp[192 + tid];
}

// ---------------- kernel 2: fused score GEMM + tanh + Va-dot -> e ----------------
// grid 2048 blocks: block handles 128 (b,l)-rows x all 64 temp cols, K=128.
#define AH_STRIDE 136
#define AW_STRIDE 72
#define ATTN2_SMEM (128 * AH_STRIDE * 2 + IND * AW_STRIDE * 2 + 64 * 8)

__global__ __launch_bounds__(256) void attn_fused(
    const float* __restrict__ ba, const float* __restrict__ Va, int t)
{
    extern __shared__ char smraw[];
    __nv_bfloat16* sA = (__nv_bfloat16*)smraw;                      // [128][136]
    __nv_bfloat16* sW = sA + 128 * AH_STRIDE;                       // [128][72]
    float2* sVC = (float2*)(smraw + 128 * AH_STRIDE * 2 + IND * AW_STRIDE * 2);

    int tid = threadIdx.x, warp = tid >> 5, lane = tid & 31;
    int m0 = blockIdx.x * 128;
    int b = m0 >> 9, l0 = m0 & 511;
    uint32_t aBase = (uint32_t)__cvta_generic_to_shared(sA);
    uint32_t wBase = (uint32_t)__cvta_generic_to_shared(sW);

    // A tile: 128 rows of H16 (2048 16B chunks)
    #pragma unroll
    for (int i = tid; i < 2048; i += 256) {
        int row = i >> 4, seg = i & 15;
        cp_async16(aBase + (uint32_t)(row * AH_STRIDE + seg * 8) * 2,
                   g_H16 + (size_t)(m0 + row) * IND + seg * 8);
    }
    // B tile: Wa_t [128][64] (1024 chunks)
    #pragma unroll
    for (int i = tid; i < 1024; i += 256) {
        int row = i >> 3, seg = i & 7;
        cp_async16(wBase + (uint32_t)(row * AW_STRIDE + seg * 8) * 2,
                   g_Wa16 + (size_t)row * (TT * TEMP) + t * TEMP + seg * 8);
    }
    cp_commit();

    if (tid < 64) {
        float cb = ba[t * 64 + tid] + g_cua[b * 64 + tid];
        sVC[tid] = make_float2(Va[tid * TT + t], cb);
    }
    cp_wait<0>();
    __syncthreads();

    // warp w owns rows [16w, 16w+16); full 64-col accumulator
    float acc[8][4];
    #pragma unroll
    for (int ni = 0; ni < 8; ni++)
        #pragma unroll
        for (int r = 0; r < 4; r++) acc[ni][r] = 0.f;

    int lr = lane & 7, lg = (lane >> 3) & 1, lc = lane >> 4;
    int R = warp * 16;
    #pragma unroll
    for (int ks = 0; ks < 8; ks++) {
        uint32_t afr[4];
        ldsm4(afr, aBase + (uint32_t)((R + lr + lg * 8) * AH_STRIDE + ks * 16 + lc * 8) * 2);
        uint32_t bfr[4][4];
        #pragma unroll
        for (int p = 0; p < 4; p++) {
            int row = ks * 16 + lr + lg * 8;
            int col = p * 16 + lc * 8;
            ldsm4t(bfr[p], wBase + (uint32_t)(row * AW_STRIDE + col) * 2);
        }
        #pragma unroll
        for (int p = 0; p < 4; p++) {
            mma_bf16(acc[2 * p],     afr, &bfr[p][0]);
            mma_bf16(acc[2 * p + 1], afr, &bfr[p][2]);
        }
    }

    // epilogue: e[l] = sum_k Va[k] * tanh(S + cUa + ba), fp16x2 tanh
    {
        int q = lane & 3, r = lane >> 2;
        float s0 = 0.f, s1 = 0.f;
        #pragma unroll
        for (int ni = 0; ni < 8; ni++) {
            int k0 = ni * 8 + q * 2;
            float2 vc0 = sVC[k0], vc1 = sVC[k0 + 1];
            float2 t0 = tanh2(acc[ni][0] + vc0.y, acc[ni][1] + vc1.y);
            s0 += vc0.x * t0.x + vc1.x * t0.y;
            float2 t1 = tanh2(acc[ni][2] + vc0.y, acc[ni][3] + vc1.y);
            s1 += vc0.x * t1.x + vc1.x * t1.y;
        }
        s0 += __shfl_xor_sync(0xffffffffu, s0, 1);
        s0 += __shfl_xor_sync(0xffffffffu, s0, 2);
        s1 += __shfl_xor_sync(0xffffffffu, s1, 1);
        s1 += __shfl_xor_sync(0xffffffffu, s1, 2);
        if (q == 0) {
            int l = l0 + R + r;
            g_e[b * SEQL + l]     = s0;
            g_e[b * SEQL + l + 8] = s1;
        }
    }
}

// ---------------- kernel 3: softmax + ctx ----------------
__global__ __launch_bounds__(256) void softmax_ctx(int t) {
    __shared__ float se[512];
    __shared__ float sctxp[2048];
    __shared__ float sred[16];

    int b = blockIdx.x, tid = threadIdx.x;
    int warp = tid >> 5, lane = tid & 31;

    float e0 = g_e[b * SEQL + tid];
    float e1 = g_e[b * SEQL + tid + 256];
    float m = fmaxf(e0, e1);
    #pragma unroll
    for (int off = 16; off; off >>= 1) m = fmaxf(m, __shfl_xor_sync(0xffffffffu, m, off));
    if (lane == 0) sred[warp] = m;
    __syncthreads();
    float M = fmaxf(fmaxf(fmaxf(sred[0], sred[1]), fmaxf(sred[2], sred[3])),
                    fmaxf(fmaxf(sred[4], sred[5]), fmaxf(sred[6], sred[7])));
    float v0 = __expf((e0 - M) * 0.0625f);
    float v1 = __expf((e1 - M) * 0.0625f);
    float s = v0 + v1;
    #pragma unroll
    for (int off = 16; off; off >>= 1) s += __shfl_xor_sync(0xffffffffu, s, off);
    if (lane == 0) sred[8 + warp] = s;
    se[tid] = v0; se[tid + 256] = v1;
    __syncthreads();
    float inv = 1.f / (sred[8] + sred[9] + sred[10] + sred[11] +
                       sred[12] + sred[13] + sred[14] + sred[15]);

    // ctx[d] = sum_l beta[l] * H[b,l,d]
    int q = tid & 15, part = tid >> 4;
    const uint4* Hp = (const uint4*)(g_H16 + (size_t)b * SEQL * IND);
    float a[8] = {0.f, 0.f, 0.f, 0.f, 0.f, 0.f, 0.f, 0.f};
    #pragma unroll 4
    for (int l = part; l < SEQL; l += 16) {
        float bl = se[l];
        uint4 v = Hp[l * 16 + q];
        const __nv_bfloat162* h2 = (const __nv_bfloat162*)&v;
        #pragma unroll
        for (int i = 0; i < 4; i++) {
            float2 f = __bfloat1622float2(h2[i]);
            a[2 * i]     += bl * f.x;
            a[2 * i + 1] += bl * f.y;
        }
    }
    #pragma unroll
    for (int i = 0; i < 8; i++) sctxp[part * 128 + q * 8 + i] = a[i];
    __syncthreads();
    if (tid < 128) {
        float sum = 0.f;
        #pragma unroll
        for (int p = 0; p < 16; p++) sum += sctxp[p * 128 + tid];
        g_ctx[b * IND + tid] = sum * inv;
    }
}

// ---------------- kernel 4: gates via tf32 mma, 64x32 tiles, 256 blocks ----------------
__global__ __launch_bounds__(256) void gates_kernel(
    const float* __restrict__ W, const float* __restrict__ U,
    const float* __restrict__ bias, const float* __restrict__ Wy, int t)
{
    __shared__ float As[2][64][36];
    __shared__ float Bs[2][32][40];
    int tid = threadIdx.x;
    int warp = tid >> 5, lane = tid & 31;
    int wm = warp & 3, wn = warp >> 2;
    int n0 = blockIdx.x * 32, b0 = blockIdx.y * 64;
    float acc[2][4] = {};

    auto copy_chunk = [&](int kc, int buf) {
        #pragma unroll
        for (int i = tid; i < 512; i += 256) {
            int row = i >> 3, seg = i & 7;
            const float* src = (kc < 4)
                ? (g_ctx + (size_t)(b0 + row) * IND + kc * 32 + seg * 4)
                : (g_h   + (size_t)(b0 + row) * HID + (kc * 32 - IND) + seg * 4);
            cp_async16((uint32_t)__cvta_generic_to_shared(&As[buf][row][seg * 4]), src);
        }
        #pragma unroll
        for (int i = tid; i < 256; i += 256) {
            int k = i >> 3, seg = i & 7;      // 8 segs x 4 = 32 cols
            int kg = kc * 32 + k;
            const float* src = (kg < IND)
                ? (W + (size_t)kg * (TT * 1024) + (size_t)t * 1024 + n0 + seg * 4)
                : (U + (size_t)(kg - IND) * (TT * 1024) + (size_t)t * 1024 + n0 + seg * 4);
            cp_async16((uint32_t)__cvta_generic_to_shared(&Bs[buf][k][seg * 4]), src);
        }
    };

    copy_chunk(0, 0); cp_commit();
    copy_chunk(1, 1); cp_commit();

    for (int kc = 0; kc < 12; kc++) {
        cp_wait<1>();
        __syncthreads();
        int buf = kc & 1;
        int ar = wm * 16 + (lane >> 2);
        int bk = lane & 3;
        int bn = wn * 16 + (lane >> 2);
        #pragma unroll
        for (int ks = 0; ks < 4; ks++) {
            uint32_t a[4];
            int ac = ks * 8 + (lane & 3);
            a[0] = f2tf32(As[buf][ar][ac]);
            a[1] = f2tf32(As[buf][ar + 8][ac]);
            a[2] = f2tf32(As[buf][ar][ac + 4]);
            a[3] = f2tf32(As[buf][ar + 8][ac + 4]);
            #pragma unroll
            for (int nt = 0; nt < 2; nt++) {
                uint32_t b0r = f2tf32(Bs[buf][ks * 8 + bk][bn + nt * 8]);
                uint32_t b1r = f2tf32(Bs[buf][ks * 8 + bk + 4][bn + nt * 8]);
                mma_tf32(acc[nt], a, b0r, b1r);
            }
        }
        __syncthreads();
        if (kc + 2 < 12) copy_chunk(kc + 2, buf);
        cp_commit();
    }

    int r0 = b0 + wm * 16 + (lane >> 2);
    float y0v = g_y[r0], y1v = g_y[r0 + 8];
    #pragma unroll
    for (int nt = 0; nt < 2; nt++) {
        int n = n0 + wn * 16 + nt * 8 + (lane & 3) * 2;
        float bb0 = bias[t * 1024 + n],   bb1 = bias[t * 1024 + n + 1];
        float wy0 = Wy[t * 1024 + n],     wy1 = Wy[t * 1024 + n + 1];
        g_gates[(size_t)r0 * 1024 + n]           = acc[nt][0] + bb0 + y0v * wy0;
        g_gates[(size_t)r0 * 1024 + n + 1]       = acc[nt][1] + bb1 + y0v * wy1;
        g_gates[(size_t)(r0 + 8) * 1024 + n]     = acc[nt][2] + bb0 + y1v * wy0;
        g_gates[(size_t)(r0 + 8) * 1024 + n + 1] = acc[nt][3] + bb1 + y1v * wy1;
    }
}

// ---------------- kernel 5: cell update + y projection + next-step cUa ----------------
__global__ void update_kernel(const float* __restrict__ fcw, const float* __restrict__ fcb,
                              const float* __restrict__ Ua, int t,
                              float* __restrict__ outy, float* __restrict__ outh)
{
    __shared__ float red[8];
    __shared__ float sc[256];
    __shared__ float sp[256];
    int b = blockIdx.x, j = threadIdx.x;
    size_t gi = (size_t)b * 1024;
    float i_ = 1.f / (1.f + __expf(-g_gates[gi + j]));
    float f_ = 1.f / (1.f + __expf(-g_gates[gi + 256 + j]));
    float gv = tanhf(g_gates[gi + 512 + j]);
    float o_ = 1.f / (1.f + __expf(-g_gates[gi + 768 + j]));
    float c = f_ * g_c[b * HID + j] + i_ * gv;
    float h = o_ * tanhf(c);
    g_c[b * HID + j] = c;
    g_h[b * HID + j] = h;
    sc[j] = c;
    outh[(size_t)b * TT * HID + (size_t)t * HID + j] = h;

    float p = h * fcw[t * HID + j];
    #pragma unroll
    for (int off = 16; off; off >>= 1) p += __shfl_xor_sync(0xffffffffu, p, off);
    int lane = j & 31, w = j >> 5;
    if (lane == 0) red[w] = p;
    __syncthreads();
    if (j == 0) {
        float ssum = red[0] + red[1] + red[2] + red[3] +
                     red[4] + red[5] + red[6] + red[7] + fcb[t];
        g_y[b] = ssum;
        outy[b * TT + t] = ssum;
    }

    // cUa for step t+1 (uniform branch)
    if (t + 1 < TT) {
        int k = j & 63, part = j >> 6;
        const float* Uc = Ua + (size_t)(t + 1) * 64 + k;
        float a = 0.f;
        int j0 = part * 64;
        #pragma unroll 8
        for (int jj = j0; jj < j0 + 64; jj++) a += sc[jj] * Uc[(size_t)jj * (TT * 64)];
        sp[part * 64 + k] = a;
        __syncthreads();
        if (j < 64) g_cua[b * 64 + j] = sp[j] + sp[64 + j] + sp[128 + j] + sp[192 + j];
    }
}

// ---------------- launch ----------------
extern "C" void kernel_launch(void* const* d_in, const int* in_sizes, int n_in,
                              void* d_out, int out_size)
{
    const float* H    = (const float*)d_in[0];
    const float* y0   = (const float*)d_in[1];
    const float* emb  = (const float*)d_in[2];
    const float* Wa   = (const float*)d_in[3];
    const float* Ua   = (const float*)d_in[4];
    const float* ba   = (const float*)d_in[5];
    const float* Va   = (const float*)d_in[6];
    const float* W    = (const float*)d_in[7];
    const float* U    = (const float*)d_in[8];
    const float* bias = (const float*)d_in[9];
    const float* Wy   = (const float*)d_in[10];
    const float* fcw  = (const float*)d_in[11];
    const float* fcb  = (const float*)d_in[12];

    float* outy = (float*)d_out;                 // (B, 24)
    float* outh = outy + (size_t)BB * TT;        // (B, 24, 256)

    cudaFuncSetAttribute(attn_fused, cudaFuncAttributeMaxDynamicSharedMemorySize, ATTN2_SMEM);

    convert_H<<<(BB * SEQL * IND / 4) / 256, 256>>>(H);
    convert_Wa<<<(IND * TT * TEMP / 4) / 256, 256>>>(Wa);
    init_state<<<BB, 256>>>(emb, y0);
    cua_init<<<BB, 256>>>(Ua);
    for (int t = 0; t < TT; t++) {
        attn_fused<<<BB * SEQL / 128, 256, ATTN2_SMEM>>>(ba, Va, t);
        softmax_ctx<<<BB, 256>>>(t);
        gates_kernel<<<dim3(32, 8), 256>>>(W, U, bias, Wy, t);
        update_kernel<<<BB, 256>>>(fcw, fcb, Ua, t, outy, outh);
    }
}

// round 7
// speedup vs baseline: 1.5710x; 1.0283x over previous
#include <cuda_runtime.h>
#include <cuda_bf16.h>
#include <cuda_fp16.h>
#include <cstdint>

#define BB   512
#define SEQL 512
#define IND  128
#define HID  256
#define TT   24
#define TEMP 64

// ---------------- persistent device scratch (no allocations) ----------------
__device__ __nv_bfloat16 g_H16[(size_t)BB * SEQL * IND];   // 67 MB, L2-resident
__device__ __nv_bfloat16 g_Wa16[IND * TT * TEMP];          // 384 KB
__device__ float g_h[BB * HID];
__device__ float g_c[BB * HID];
__device__ float g_y[BB];
__device__ float g_cua[BB * TEMP];                         // c_t @ Ua_t
__device__ float g_ctxp[BB * 4 * IND];                     // per-block ctx partials (1 MB)
__device__ float g_psum[BB * 4];                           // per-block exp-sum partials
__device__ float g_ctx[BB * IND];
__device__ float g_gates[BB * 4 * HID];

// ---------------- asm helpers ----------------
__device__ __forceinline__ void ldsm4(uint32_t* r, uint32_t a) {
    asm volatile("ldmatrix.sync.aligned.m8n8.x4.shared.b16 {%0,%1,%2,%3}, [%4];\n"
        : "=r"(r[0]), "=r"(r[1]), "=r"(r[2]), "=r"(r[3]) : "r"(a));
}
__device__ __forceinline__ void ldsm4t(uint32_t* r, uint32_t a) {
    asm volatile("ldmatrix.sync.aligned.m8n8.x4.trans.shared.b16 {%0,%1,%2,%3}, [%4];\n"
        : "=r"(r[0]), "=r"(r[1]), "=r"(r[2]), "=r"(r[3]) : "r"(a));
}
__device__ __forceinline__ void mma_bf16(float* d, const uint32_t* a, const uint32_t* b) {
    asm volatile("mma.sync.aligned.m16n8k16.row.col.f32.bf16.bf16.f32 "
        "{%0,%1,%2,%3}, {%4,%5,%6,%7}, {%8,%9}, {%0,%1,%2,%3};\n"
        : "+f"(d[0]), "+f"(d[1]), "+f"(d[2]), "+f"(d[3])
        : "r"(a[0]), "r"(a[1]), "r"(a[2]), "r"(a[3]), "r"(b[0]), "r"(b[1]));
}
__device__ __forceinline__ void mma_tf32(float* d, const uint32_t* a, uint32_t b0, uint32_t b1) {
    asm volatile("mma.sync.aligned.m16n8k8.row.col.f32.tf32.tf32.f32 "
        "{%0,%1,%2,%3}, {%4,%5,%6,%7}, {%8,%9}, {%0,%1,%2,%3};\n"
        : "+f"(d[0]), "+f"(d[1]), "+f"(d[2]), "+f"(d[3])
        : "r"(a[0]), "r"(a[1]), "r"(a[2]), "r"(a[3]), "r"(b0), "r"(b1));
}
__device__ __forceinline__ uint32_t f2tf32(float v) {
    uint32_t u; asm("cvt.rna.tf32.f32 %0, %1;" : "=r"(u) : "f"(v)); return u;
}
__device__ __forceinline__ float2 tanh2(float x0, float x1) {
    uint32_t r;
    asm("{\n\t.reg .b32 p;\n\tcvt.rn.f16x2.f32 p, %1, %2;\n\ttanh.approx.f16x2 %0, p;\n\t}"
        : "=r"(r) : "f"(x1), "f"(x0));
    __half2 h = *reinterpret_cast<__half2*>(&r);
    return __half22float2(h);
}
__device__ __forceinline__ void cp_async16(uint32_t dst, const void* src) {
    asm volatile("cp.async.cg.shared.global [%0], [%1], 16;\n" :: "r"(dst), "l"(src));
}
__device__ __forceinline__ void cp_commit() {
    asm volatile("cp.async.commit_group;\n" ::: "memory");
}
template<int N> __device__ __forceinline__ void cp_wait() {
    asm volatile("cp.async.wait_group %0;\n" :: "n"(N) : "memory");
}
__device__ __forceinline__ uint32_t pack_bf16x2(float a, float b) {
    __nv_bfloat162 p = __floats2bfloat162_rn(a, b);
    return *(const uint32_t*)&p;
}

// ---------------- converts ----------------
__global__ void convert_H(const float* __restrict__ H) {
    int i = blockIdx.x * blockDim.x + threadIdx.x;
    float4 v = ((const float4*)H)[i];
    uint2 o;
    o.x = pack_bf16x2(v.x, v.y);
    o.y = pack_bf16x2(v.z, v.w);
    ((uint2*)g_H16)[i] = o;
}
__global__ void convert_Wa(const float* __restrict__ Wa) {
    int i = blockIdx.x * blockDim.x + threadIdx.x;
    float4 v = ((const float4*)Wa)[i];
    uint2 o;
    o.x = pack_bf16x2(v.x, v.y);
    o.y = pack_bf16x2(v.z, v.w);
    ((uint2*)g_Wa16)[i] = o;
}

// ---------------- init: state + cUa(t=0) ----------------
__global__ void init_state(const float* __restrict__ emb, const float* __restrict__ y0,
                           const float* __restrict__ Ua) {
    __shared__ float sc[256];
    __shared__ float sp[256];
    int b = blockIdx.x, j = threadIdx.x;
    float h = emb[b * 2 * HID + j];
    float c = emb[b * 2 * HID + HID + j];
    g_h[b * HID + j] = h;
    g_c[b * HID + j] = c;
    sc[j] = c;
    if (j == 0) g_y[b] = y0[b];
    __syncthreads();
    int k = j & 63, part = j >> 6;
    const float* Uc = Ua + k;          // t = 0
    float a = 0.f;
    int j0 = part * 64;
    #pragma unroll 8
    for (int jj = j0; jj < j0 + 64; jj++) a += sc[jj] * Uc[(size_t)jj * (TT * 64)];
    sp[part * 64 + k] = a;
    __syncthreads();
    if (j < 64) g_cua[b * 64 + j] = sp[j] + sp[64 + j] + sp[128 + j] + sp[192 + j];
}

// ---------------- fused attention: GEMM + tanh + Va-dot + exp + partial ctx ----------------
// grid 2048: block = 128 (b,l)-rows x 64 temp cols, K=128. Max-free softmax.
#define AH_STRIDE 136
#define AW_STRIDE 72
// layout: sA [128][136] bf16 | sW [128][72] bf16 (aliased by sctxp after mma) | sVC 64 f2 | se 128 f
#define ATTN2_SMEM (128 * AH_STRIDE * 2 + IND * AW_STRIDE * 2 + 64 * 8 + 128 * 4)

__global__ __launch_bounds__(256) void attn_fused(
    const float* __restrict__ ba, const float* __restrict__ Va, int t)
{
    extern __shared__ char smraw[];
    __nv_bfloat16* sA = (__nv_bfloat16*)smraw;                      // [128][136]
    __nv_bfloat16* sW = sA + 128 * AH_STRIDE;                       // [128][72]
    float* sctxp = (float*)sW;                                      // 16x128 floats (8KB <= 18KB), after mma
    float2* sVC = (float2*)(smraw + 128 * AH_STRIDE * 2 + IND * AW_STRIDE * 2);
    float* se = (float*)(sVC + 64);                                 // 128 p-values

    int tid = threadIdx.x, warp = tid >> 5, lane = tid & 31;
    int m0 = blockIdx.x * 128;
    int b = m0 >> 9;
    int blkInB = blockIdx.x & 3;
    uint32_t aBase = (uint32_t)__cvta_generic_to_shared(sA);
    uint32_t wBase = (uint32_t)__cvta_generic_to_shared(sW);

    #pragma unroll
    for (int i = tid; i < 2048; i += 256) {
        int row = i >> 4, seg = i & 15;
        cp_async16(aBase + (uint32_t)(row * AH_STRIDE + seg * 8) * 2,
                   g_H16 + (size_t)(m0 + row) * IND + seg * 8);
    }
    #pragma unroll
    for (int i = tid; i < 1024; i += 256) {
        int row = i >> 3, seg = i & 7;
        cp_async16(wBase + (uint32_t)(row * AW_STRIDE + seg * 8) * 2,
                   g_Wa16 + (size_t)row * (TT * TEMP) + t * TEMP + seg * 8);
    }
    cp_commit();

    if (tid < 64) {
        float cb = ba[t * 64 + tid] + g_cua[b * 64 + tid];
        sVC[tid] = make_float2(Va[tid * TT + t], cb);
    }
    cp_wait<0>();
    __syncthreads();

    // warp w owns rows [16w, 16w+16)
    float acc[8][4];
    #pragma unroll
    for (int ni = 0; ni < 8; ni++)
        #pragma unroll
        for (int r = 0; r < 4; r++) acc[ni][r] = 0.f;

    int lr = lane & 7, lg = (lane >> 3) & 1, lc = lane >> 4;
    int R = warp * 16;
    #pragma unroll
    for (int ks = 0; ks < 8; ks++) {
        uint32_t afr[4];
        ldsm4(afr, aBase + (uint32_t)((R + lr + lg * 8) * AH_STRIDE + ks * 16 + lc * 8) * 2);
        uint32_t bfr[4][4];
        #pragma unroll
        for (int p = 0; p < 4; p++) {
            int row = ks * 16 + lr + lg * 8;
            int col = p * 16 + lc * 8;
            ldsm4t(bfr[p], wBase + (uint32_t)(row * AW_STRIDE + col) * 2);
        }
        #pragma unroll
        for (int p = 0; p < 4; p++) {
            mma_bf16(acc[2 * p],     afr, &bfr[p][0]);
            mma_bf16(acc[2 * p + 1], afr, &bfr[p][2]);
        }
    }

    // epilogue: p[l] = exp( (sum_k Va[k]*tanh(S+cUa+ba)) / 16 ), max-free (|e|<~3)
    {
        int q = lane & 3, r = lane >> 2;
        float s0 = 0.f, s1 = 0.f;
        #pragma unroll
        for (int ni = 0; ni < 8; ni++) {
            int k0 = ni * 8 + q * 2;
            float2 vc0 = sVC[k0], vc1 = sVC[k0 + 1];
            float2 t0 = tanh2(acc[ni][0] + vc0.y, acc[ni][1] + vc1.y);
            s0 += vc0.x * t0.x + vc1.x * t0.y;
            float2 t1 = tanh2(acc[ni][2] + vc0.y, acc[ni][3] + vc1.y);
            s1 += vc0.x * t1.x + vc1.x * t1.y;
        }
        s0 += __shfl_xor_sync(0xffffffffu, s0, 1);
        s0 += __shfl_xor_sync(0xffffffffu, s0, 2);
        s1 += __shfl_xor_sync(0xffffffffu, s1, 1);
        s1 += __shfl_xor_sync(0xffffffffu, s1, 2);
        if (q == 0) {
            se[R + r]     = __expf(s0 * 0.0625f);
            se[R + r + 8] = __expf(s1 * 0.0625f);
        }
    }
    __syncthreads();   // se complete; sW no longer read -> sctxp may overwrite it

    // psum partial for this block
    if (tid < 32) {
        float p = se[tid] + se[tid + 32] + se[tid + 64] + se[tid + 96];
        #pragma unroll
        for (int off = 16; off; off >>= 1) p += __shfl_xor_sync(0xffffffffu, p, off);
        if (tid == 0) g_psum[b * 4 + blkInB] = p;
    }

    // ctx partial: ctxp[d] = sum_{l in block} p[l] * H[l,d]  (H from smem tile)
    {
        int q = tid & 15, part = tid >> 4;
        float a[8] = {0.f, 0.f, 0.f, 0.f, 0.f, 0.f, 0.f, 0.f};
        #pragma unroll
        for (int r = 0; r < 8; r++) {
            int row = part * 8 + r;
            float pl = se[row];
            uint4 v = *(const uint4*)(sA + row * AH_STRIDE + q * 8);
            const __nv_bfloat162* h2 = (const __nv_bfloat162*)&v;
            #pragma unroll
            for (int i = 0; i < 4; i++) {
                float2 f = __bfloat1622float2(h2[i]);
                a[2 * i]     += pl * f.x;
                a[2 * i + 1] += pl * f.y;
            }
        }
        #pragma unroll
        for (int i = 0; i < 8; i++) sctxp[part * 128 + q * 8 + i] = a[i];
        __syncthreads();
        if (tid < 128) {
            float sum = 0.f;
            #pragma unroll
            for (int p = 0; p < 16; p++) sum += sctxp[p * 128 + tid];
            g_ctxp[(size_t)(b * 4 + blkInB) * IND + tid] = sum;
        }
    }
}

// ---------------- normalize: ctx = (sum of 4 ctx partials) / (sum of 4 psums) ----------------
__global__ void normalize_ctx() {
    __shared__ float sinv;
    int b = blockIdx.x, d = threadIdx.x;   // 128 threads
    if (d == 0) {
        sinv = 1.f / (g_psum[b * 4] + g_psum[b * 4 + 1] + g_psum[b * 4 + 2] + g_psum[b * 4 + 3]);
    }
    __syncthreads();
    const float* cp = g_ctxp + (size_t)b * 4 * IND;
    g_ctx[b * IND + d] = (cp[d] + cp[IND + d] + cp[2 * IND + d] + cp[3 * IND + d]) * sinv;
}

// ---------------- gates via tf32 mma, 64x32 tiles ----------------
__global__ __launch_bounds__(256) void gates_kernel(
    const float* __restrict__ W, const float* __restrict__ U,
    const float* __restrict__ bias, const float* __restrict__ Wy, int t)
{
    __shared__ float As[2][64][36];
    __shared__ float Bs[2][32][40];
    int tid = threadIdx.x;
    int warp = tid >> 5, lane = tid & 31;
    int wm = warp & 3, wn = warp >> 2;
    int n0 = blockIdx.x * 32, b0 = blockIdx.y * 64;
    float acc[2][4] = {};

    auto copy_chunk = [&](int kc, int buf) {
        #pragma unroll
        for (int i = tid; i < 512; i += 256) {
            int row = i >> 3, seg = i & 7;
            const float* src = (kc < 4)
                ? (g_ctx + (size_t)(b0 + row) * IND + kc * 32 + seg * 4)
                : (g_h   + (size_t)(b0 + row) * HID + (kc * 32 - IND) + seg * 4);
            cp_async16((uint32_t)__cvta_generic_to_shared(&As[buf][row][seg * 4]), src);
        }
        {
            int k = tid >> 3, seg = tid & 7;
            if (tid < 256) {
                int kg = kc * 32 + k;
                const float* src = (kg < IND)
                    ? (W + (size_t)kg * (TT * 1024) + (size_t)t * 1024 + n0 + seg * 4)
                    : (U + (size_t)(kg - IND) * (TT * 1024) + (size_t)t * 1024 + n0 + seg * 4);
                cp_async16((uint32_t)__cvta_generic_to_shared(&Bs[buf][k][seg * 4]), src);
            }
        }
    };

    copy_chunk(0, 0); cp_commit();
    copy_chunk(1, 1); cp_commit();

    for (int kc = 0; kc < 12; kc++) {
        cp_wait<1>();
        __syncthreads();
        int buf = kc & 1;
        int ar = wm * 16 + (lane >> 2);
        int bk = lane & 3;
        int bn = wn * 16 + (lane >> 2);
        #pragma unroll
        for (int ks = 0; ks < 4; ks++) {
            uint32_t a[4];
            int ac = ks * 8 + (lane & 3);
            a[0] = f2tf32(As[buf][ar][ac]);
            a[1] = f2tf32(As[buf][ar + 8][ac]);
            a[2] = f2tf32(As[buf][ar][ac + 4]);
            a[3] = f2tf32(As[buf][ar + 8][ac + 4]);
            #pragma unroll
            for (int nt = 0; nt < 2; nt++) {
                uint32_t b0r = f2tf32(Bs[buf][ks * 8 + bk][bn + nt * 8]);
                uint32_t b1r = f2tf32(Bs[buf][ks * 8 + bk + 4][bn + nt * 8]);
                mma_tf32(acc[nt], a, b0r, b1r);
            }
        }
        __syncthreads();
        if (kc + 2 < 12) copy_chunk(kc + 2, buf);
        cp_commit();
    }

    int r0 = b0 + wm * 16 + (lane >> 2);
    float y0v = g_y[r0], y1v = g_y[r0 + 8];
    #pragma unroll
    for (int nt = 0; nt < 2; nt++) {
        int n = n0 + wn * 16 + nt * 8 + (lane & 3) * 2;
        float bb0 = bias[t * 1024 + n],   bb1 = bias[t * 1024 + n + 1];
        float wy0 = Wy[t * 1024 + n],     wy1 = Wy[t * 1024 + n + 1];
        g_gates[(size_t)r0 * 1024 + n]           = acc[nt][0] + bb0 + y0v * wy0;
        g_gates[(size_t)r0 * 1024 + n + 1]       = acc[nt][1] + bb1 + y0v * wy1;
        g_gates[(size_t)(r0 + 8) * 1024 + n]     = acc[nt][2] + bb0 + y1v * wy0;
        g_gates[(size_t)(r0 + 8) * 1024 + n + 1] = acc[nt][3] + bb1 + y1v * wy1;
    }
}

// ---------------- update: cell + y proj + next-step cUa ----------------
__global__ void update_kernel(const float* __restrict__ fcw, const float* __restrict__ fcb,
                              const float* __restrict__ Ua, int t,
                              float* __restrict__ outy, float* __restrict__ outh)
{
    __shared__ float red[8];
    __shared__ float sc[256];
    __shared__ float sp[256];
    int b = blockIdx.x, j = threadIdx.x;
    size_t gi = (size_t)b * 1024;
    float i_ = 1.f / (1.f + __expf(-g_gates[gi + j]));
    float f_ = 1.f / (1.f + __expf(-g_gates[gi + 256 + j]));
    float gv = tanhf(g_gates[gi + 512 + j]);
    float o_ = 1.f / (1.f + __expf(-g_gates[gi + 768 + j]));
    float c = f_ * g_c[b * HID + j] + i_ * gv;
    float h = o_ * tanhf(c);
    g_c[b * HID + j] = c;
    g_h[b * HID + j] = h;
    sc[j] = c;
    outh[(size_t)b * TT * HID + (size_t)t * HID + j] = h;

    float p = h * fcw[t * HID + j];
    #pragma unroll
    for (int off = 16; off; off >>= 1) p += __shfl_xor_sync(0xffffffffu, p, off);
    int lane = j & 31, w = j >> 5;
    if (lane == 0) red[w] = p;
    __syncthreads();
    if (j == 0) {
        float ssum = red[0] + red[1] + red[2] + red[3] +
                     red[4] + red[5] + red[6] + red[7] + fcb[t];
        g_y[b] = ssum;
        outy[b * TT + t] = ssum;
    }

    if (t + 1 < TT) {
        int k = j & 63, part = j >> 6;
        const float* Uc = Ua + (size_t)(t + 1) * 64 + k;
        float a = 0.f;
        int j0 = part * 64;
        #pragma unroll 8
        for (int jj = j0; jj < j0 + 64; jj++) a += sc[jj] * Uc[(size_t)jj * (TT * 64)];
        sp[part * 64 + k] = a;
        __syncthreads();
        if (j < 64) g_cua[b * 64 + j] = sp[j] + sp[64 + j] + sp[128 + j] + sp[192 + j];
    }
}

// ---------------- launch ----------------
extern "C" void kernel_launch(void* const* d_in, const int* in_sizes, int n_in,
                              void* d_out, int out_size)
{
    const float* H    = (const float*)d_in[0];
    const float* y0   = (const float*)d_in[1];
    const float* emb  = (const float*)d_in[2];
    const float* Wa   = (const float*)d_in[3];
    const float* Ua   = (const float*)d_in[4];
    const float* ba   = (const float*)d_in[5];
    const float* Va   = (const float*)d_in[6];
    const float* W    = (const float*)d_in[7];
    const float* U    = (const float*)d_in[8];
    const float* bias = (const float*)d_in[9];
    const float* Wy   = (const float*)d_in[10];
    const float* fcw  = (const float*)d_in[11];
    const float* fcb  = (const float*)d_in[12];

    float* outy = (float*)d_out;                 // (B, 24)
    float* outh = outy + (size_t)BB * TT;        // (B, 24, 256)

    cudaFuncSetAttribute(attn_fused, cudaFuncAttributeMaxDynamicSharedMemorySize, ATTN2_SMEM);

    convert_H<<<(BB * SEQL * IND / 4) / 256, 256>>>(H);
    convert_Wa<<<(IND * TT * TEMP / 4) / 256, 256>>>(Wa);
    init_state<<<BB, 256>>>(emb, y0, Ua);
    for (int t = 0; t < TT; t++) {
        attn_fused<<<BB * SEQL / 128, 256, ATTN2_SMEM>>>(ba, Va, t);
        normalize_ctx<<<BB, 128>>>();
        gates_kernel<<<dim3(32, 8), 256>>>(W, U, bias, Wy, t);
        update_kernel<<<BB, 256>>>(fcw, fcb, Ua, t, outy, outh);
    }
}